// round 7
// baseline (speedup 1.0000x reference)
#include <cuda_runtime.h>
#include <cuda_fp16.h>
#include <math.h>

// RegionalAttentionPool: B=16, N=4096, D=512, R=64, K=128
// Single persistent kernel, software-pipelined over 4 stages of 4 batches:
//   stage s: convert+score batches [4s,4s+4)   (DRAM-bound: read x, write fp16)
//   then pool stage s-1                        (L2-bound: gather fp16 rows)
// Convert of stage s overlaps chip-wide with pool of stage s-1, so the DRAM
// stream and the L2 gather run concurrently instead of sequentially.

constexpr int Bc = 16;
constexpr int Nc = 4096;
constexpr int Dc = 512;
constexpr int Rc = 64;
constexpr int Kc = 128;

constexpr int NCTA   = 256;    // all resident: 256 <= 148 SMs * occ 2
constexpr int NTHR   = 512;
constexpr int STAGES = 4;
constexpr int BPS    = Bc / STAGES;                 // 4 batches per stage
constexpr int ROWS_PER_STAGE = BPS * Nc;            // 16384
constexpr int ROWS_PER_CTA   = ROWS_PER_STAGE / NCTA; // 64

__device__ float  g_scores[Bc * Nc];                  // 256 KB
__device__ __half g_xh[(size_t)Bc * Nc * Dc];         // 64 MiB fp16 copy of x
__device__ int    g_cnt[STAGES];                      // stage arrival counters

// ---------------------------------------------------------------------------
__device__ __forceinline__ void pool_stage(
    int s, int cta, int tid, int lane, int warp,
    const int* __restrict__ ridx, float4* __restrict__ out4,
    float* s_w, int* s_base, float* s_m, float4 (*s_red)[128])
{
    const int b = s * BPS + (cta >> 6);
    const int r = cta & 63;

    // --- softmax over 128 gathered scores (threads 0..127, one per k) ---
    float sc = -3.402823466e38f;
    if (tid < Kc) {
        const int idx = __ldg(&ridx[r * Kc + tid]);
        s_base[tid] = (b * Nc + idx) * (Dc / 4);    // row start in uint2 units
        sc = __ldcg(&g_scores[b * Nc + idx]);
    }
    float m = sc;
    #pragma unroll
    for (int off = 16; off > 0; off >>= 1)
        m = fmaxf(m, __shfl_xor_sync(0xffffffffu, m, off));
    if (lane == 0 && warp < 4) s_m[warp] = m;
    __syncthreads();
    const float mall = fmaxf(fmaxf(s_m[0], s_m[1]), fmaxf(s_m[2], s_m[3]));

    float e = (tid < Kc) ? __expf(sc - mall) : 0.0f;
    float l = e;
    #pragma unroll
    for (int off = 16; off > 0; off >>= 1)
        l += __shfl_xor_sync(0xffffffffu, l, off);
    __syncthreads();                    // s_m reuse hazard
    if (lane == 0 && warp < 4) s_m[warp] = l;
    __syncthreads();
    const float lall = (s_m[0] + s_m[1]) + (s_m[2] + s_m[3]);
    if (tid < Kc) s_w[tid] = e / lall;
    __syncthreads();

    // --- weighted sum: sub-group handles 32 of the 128 rows, MLP=8 ---
    const uint2* __restrict__ xh2 = (const uint2*)g_xh;
    const int sub = tid >> 7;           // 0..3
    const int dp  = tid & 127;          // uint2 (4 halfs) within row

    float ax = 0.f, ay = 0.f, az = 0.f, aw = 0.f;
    #pragma unroll 1
    for (int g = 0; g < 32; g += 8) {
        uint2 v[8];
        #pragma unroll
        for (int j = 0; j < 8; j++)
            v[j] = __ldcg(&xh2[(size_t)s_base[sub * 32 + g + j] + dp]);
        #pragma unroll
        for (int j = 0; j < 8; j++) {
            const float wk = s_w[sub * 32 + g + j];
            float2 f0 = __half22float2(*(__half2*)&v[j].x);
            float2 f1 = __half22float2(*(__half2*)&v[j].y);
            ax = fmaf(wk, f0.x, ax);
            ay = fmaf(wk, f0.y, ay);
            az = fmaf(wk, f1.x, az);
            aw = fmaf(wk, f1.y, aw);
        }
    }

    if (sub > 0) s_red[sub - 1][dp] = make_float4(ax, ay, az, aw);
    __syncthreads();
    if (sub == 0) {
        float4 t0 = s_red[0][dp], t1 = s_red[1][dp], t2 = s_red[2][dp];
        ax += t0.x + t1.x + t2.x;
        ay += t0.y + t1.y + t2.y;
        az += t0.z + t1.z + t2.z;
        aw += t0.w + t1.w + t2.w;
        out4[(size_t)(b * Rc + r) * 128 + dp] = make_float4(ax, ay, az, aw);
    }
    __syncthreads();                    // protect s_w/s_base for next stage
}

// ---------------------------------------------------------------------------
__global__ __launch_bounds__(NTHR, 2)
void fused_pipeline(const float4* __restrict__ x4,
                    const int*    __restrict__ ridx,
                    const float4* __restrict__ W4,
                    const float*  __restrict__ bias,
                    float4*       __restrict__ out4)
{
    __shared__ float  s_w[Kc];
    __shared__ int    s_base[Kc];
    __shared__ float  s_m[4];
    __shared__ float4 s_red[3][128];

    const int tid  = threadIdx.x;
    const int lane = tid & 31;
    const int warp = tid >> 5;          // 0..15
    const int cta  = blockIdx.x;

    // hoist W into registers (lane-resident)
    float4 wv[4];
    #pragma unroll
    for (int j = 0; j < 4; j++) wv[j] = W4[j * 32 + lane];
    const float b0 = bias[0];

    uint2* __restrict__ xh2w = (uint2*)g_xh;

    for (int s = 0; s < STAGES; s++) {
        // ---- convert + score: 64 rows per CTA, 1 warp per row ----
        const int rbase = s * ROWS_PER_STAGE + cta * ROWS_PER_CTA;
        #pragma unroll 1
        for (int i = 0; i < ROWS_PER_CTA / 16; i++) {
            const int row = rbase + i * 16 + warp;
            const float4* __restrict__ xr = x4 + (size_t)row * 128;
            uint2* __restrict__ xo = xh2w + (size_t)row * 128;

            float dot = 0.0f;
            #pragma unroll
            for (int j = 0; j < 4; j++) {
                float4 v = __ldcs(&xr[j * 32 + lane]);   // streaming read
                dot = fmaf(v.x, wv[j].x, dot);
                dot = fmaf(v.y, wv[j].y, dot);
                dot = fmaf(v.z, wv[j].z, dot);
                dot = fmaf(v.w, wv[j].w, dot);
                __half2 h0 = __floats2half2_rn(v.x, v.y);
                __half2 h1 = __floats2half2_rn(v.z, v.w);
                uint2 p;
                p.x = *(unsigned int*)&h0;
                p.y = *(unsigned int*)&h1;
                xo[j * 32 + lane] = p;
            }
            #pragma unroll
            for (int off = 16; off > 0; off >>= 1)
                dot += __shfl_xor_sync(0xffffffffu, dot, off);
            if (lane == 0) g_scores[row] = dot + b0;
        }
        __syncthreads();
        if (tid == 0) {
            __threadfence();
            atomicAdd(&g_cnt[s], 1);
        }

        if (s > 0) {
            if (tid == 0) {
                volatile int* c = &g_cnt[s - 1];
                while (*c < NCTA) __nanosleep(64);
            }
            __syncthreads();
            pool_stage(s - 1, cta, tid, lane, warp, ridx, out4,
                       s_w, s_base, s_m, s_red);
        }
    }

    if (tid == 0) {
        volatile int* c = &g_cnt[STAGES - 1];
        while (*c < NCTA) __nanosleep(64);
    }
    __syncthreads();
    pool_stage(STAGES - 1, cta, tid, lane, warp, ridx, out4,
               s_w, s_base, s_m, s_red);
}

extern "C" void kernel_launch(void* const* d_in, const int* in_sizes, int n_in,
                              void* d_out, int out_size)
{
    const float4* x4   = (const float4*)d_in[0];   // (B, N, D) f32
    const int*    ridx = (const int*)   d_in[1];   // (R, K) i32
    const float4* W4   = (const float4*)d_in[2];   // (1, D) f32
    const float*  bias = (const float*) d_in[3];   // (1,) f32

    int* cnt = nullptr;
    cudaGetSymbolAddress((void**)&cnt, g_cnt);
    cudaMemsetAsync(cnt, 0, sizeof(int) * STAGES);

    fused_pipeline<<<NCTA, NTHR>>>(x4, ridx, W4, bias, (float4*)d_out);
    (void)in_sizes; (void)n_in; (void)out_size;
}

// round 8
// speedup vs baseline: 1.3003x; 1.3003x over previous
#include <cuda_runtime.h>
#include <cuda_fp16.h>
#include <math.h>

// RegionalAttentionPool: B=16, N=4096, D=512, R=64, K=128
// Pass 1 (score+convert): stream x once with __ldcs (no L2 pollution),
//   compute scores y[b,n] = x.W + bias, write fp16 copy of x with default
//   caching -> the 64 MB fp16 copy stays resident in the 126 MB L2.
// Pass 2 (pool): per-(b,r) softmax over gathered scores, then weighted sum
//   gathering fp16 rows from L2 (__ldcg), two 64-k teams per CTA.

constexpr int Bc = 16;
constexpr int Nc = 4096;
constexpr int Dc = 512;
constexpr int Rc = 64;
constexpr int Kc = 128;
constexpr int D4 = Dc / 4;      // 128 float4 per fp32 row
constexpr int DH2 = Dc / 4;     // 128 uint2 (4 halfs) per fp16 row

__device__ float  g_scores[Bc * Nc];            // 256 KB
__device__ __half g_xh[(size_t)Bc * Nc * Dc];   // 64 MiB fp16 copy of x

// ---------------------------------------------------------------------------
// Pass 1: one warp per row, 16 rows/CTA (512 threads).
// ---------------------------------------------------------------------------
__global__ __launch_bounds__(512, 2)
void score_convert_pass(const float4* __restrict__ x4,
                        const float4* __restrict__ W4,
                        const float*  __restrict__ bias,
                        float*        __restrict__ y)
{
    const int lane = threadIdx.x & 31;
    const int warp = threadIdx.x >> 5;                 // 0..15
    const int row  = blockIdx.x * 16 + warp;           // 0 .. B*N-1

    const float4* __restrict__ xr = x4 + (size_t)row * D4;
    uint2* __restrict__ xo = (uint2*)(g_xh + (size_t)row * Dc);

    float dot = 0.0f;
    #pragma unroll
    for (int j = 0; j < 4; j++) {
        float4 v = __ldcs(&xr[j * 32 + lane]);         // streaming: bypass L2 fill
        float4 w = W4[j * 32 + lane];
        dot = fmaf(v.x, w.x, dot);
        dot = fmaf(v.y, w.y, dot);
        dot = fmaf(v.z, w.z, dot);
        dot = fmaf(v.w, w.w, dot);

        __half2 h0 = __floats2half2_rn(v.x, v.y);
        __half2 h1 = __floats2half2_rn(v.z, v.w);
        uint2 p;
        p.x = *(unsigned int*)&h0;
        p.y = *(unsigned int*)&h1;
        xo[j * 32 + lane] = p;                          // default: L2-resident
    }
    #pragma unroll
    for (int off = 16; off > 0; off >>= 1)
        dot += __shfl_xor_sync(0xffffffffu, dot, off);

    if (lane == 0) y[row] = dot + bias[0];
}

// ---------------------------------------------------------------------------
// Pass 2: one CTA per (b,r), 256 threads = 2 k-teams of 128.
// Thread = one uint2 (4 halfs) of the row; team t covers k in [64t, 64t+64).
// ---------------------------------------------------------------------------
__global__ __launch_bounds__(256)
void pool_pass(const int*   __restrict__ ridx,
               const float* __restrict__ y,
               float4*      __restrict__ out4)
{
    __shared__ float  s_w[Kc];
    __shared__ int    s_base[Kc];       // row start offsets (uint2 units)
    __shared__ float  s_red[4];
    __shared__ float4 s_acc[128];       // team-1 partials

    const int tid  = threadIdx.x;       // 0..255
    const int lane = tid & 31;
    const int warp = tid >> 5;          // 0..7
    const int team = tid >> 7;          // 0..1
    const int dp   = tid & 127;         // uint2 index within row
    const int r    = blockIdx.x % Rc;
    const int b    = blockIdx.x / Rc;

    // --- softmax over 128 gathered scores (warps 0..3 hold the data) ---
    const int k = tid & 127;            // upper team duplicates lower's work
    const int idx = __ldg(&ridx[r * Kc + k]);
    if (tid < Kc) s_base[tid] = (b * Nc + idx) * DH2;
    const float s = __ldcg(&y[b * Nc + idx]);

    float m = s;
    #pragma unroll
    for (int off = 16; off > 0; off >>= 1)
        m = fmaxf(m, __shfl_xor_sync(0xffffffffu, m, off));
    if (lane == 0 && warp < 4) s_red[warp] = m;
    __syncthreads();
    m = fmaxf(fmaxf(s_red[0], s_red[1]), fmaxf(s_red[2], s_red[3]));

    const float e = __expf(s - m);
    float l = e;
    #pragma unroll
    for (int off = 16; off > 0; off >>= 1)
        l += __shfl_xor_sync(0xffffffffu, l, off);
    __syncthreads();                    // s_red reuse hazard
    if (lane == 0 && warp < 4) s_red[warp] = l;
    __syncthreads();
    l = (s_red[0] + s_red[1]) + (s_red[2] + s_red[3]);
    if (tid < Kc) s_w[tid] = e / l;
    __syncthreads();

    // --- weighted sum: each team does 64 rows, MLP=8, fp16 loads from L2 ---
    const uint2* __restrict__ xh = (const uint2*)g_xh;
    const int kbase = team * 64;

    float ax = 0.f, ay = 0.f, az = 0.f, aw = 0.f;
    #pragma unroll 1
    for (int g = 0; g < 64; g += 8) {
        uint2 v[8];
        #pragma unroll
        for (int j = 0; j < 8; j++)
            v[j] = __ldcg(&xh[(size_t)s_base[kbase + g + j] + dp]);
        #pragma unroll
        for (int j = 0; j < 8; j++) {
            const float wk = s_w[kbase + g + j];
            float2 f0 = __half22float2(*(__half2*)&v[j].x);
            float2 f1 = __half22float2(*(__half2*)&v[j].y);
            ax = fmaf(wk, f0.x, ax);
            ay = fmaf(wk, f0.y, ay);
            az = fmaf(wk, f1.x, az);
            aw = fmaf(wk, f1.y, aw);
        }
    }

    if (team == 1) s_acc[dp] = make_float4(ax, ay, az, aw);
    __syncthreads();
    if (team == 0) {
        float4 t = s_acc[dp];
        out4[(size_t)blockIdx.x * 128 + dp] =
            make_float4(ax + t.x, ay + t.y, az + t.z, aw + t.w);
    }
}

extern "C" void kernel_launch(void* const* d_in, const int* in_sizes, int n_in,
                              void* d_out, int out_size)
{
    const float4* x4   = (const float4*)d_in[0];   // (B, N, D) f32
    const int*    ridx = (const int*)   d_in[1];   // (R, K) i32
    const float4* W4   = (const float4*)d_in[2];   // (1, D) f32
    const float*  bias = (const float*) d_in[3];   // (1,) f32

    float* y = nullptr;
    cudaGetSymbolAddress((void**)&y, g_scores);

    score_convert_pass<<<(Bc * Nc) / 16, 512>>>(x4, W4, bias, y);
    pool_pass<<<Bc * Rc, 256>>>(ridx, y, (float4*)d_out);
    (void)in_sizes; (void)n_in; (void)out_size;
}